// round 5
// baseline (speedup 1.0000x reference)
#include <cuda_runtime.h>
#include <math_constants.h>

// Problem constants (fixed shapes from setup_inputs)
#define BB   8      // batch
#define NPTS 256    // N = 4096/16
#define BETA 192    // 0.75*N
#define KN   768    // 3*N oversampled points
#define CO   128    // out channels
#define HO   256
#define WO   256
#define CF   64     // res2 channels
#define HF   512
#define WF   512
#define CFEAT (CO + CF)   // 192
#define PTS 8             // points per GEMM block

__device__ float g_unc2[BB * KN * 2];                        // per-row partials
__device__ __align__(16) float g_featT[BB * CFEAT * NPTS];   // [B, 192, N]

#define PACK_F32X2(out, lo, hi) \
    asm("mov.b64 %0, {%1, %2};" : "=l"(out) : "f"(lo), "f"(hi))
#define FFMA2(acc, a, b) \
    asm("fma.rn.f32x2 %0, %1, %2, %0;" : "+l"(acc) : "l"(a), "l"(b))

// merge running top2 (m1>=m2) with single value v
__device__ __forceinline__ void merge1(float &m1, float &m2, float v) {
    float n1 = fmaxf(m1, v);
    m2 = fmaxf(fminf(m1, v), m2);
    m1 = n1;
}
// merge running top2 with another pair (o1>=o2)
__device__ __forceinline__ void merge2(float &m1, float &m2, float o1, float o2) {
    float n1 = fmaxf(m1, o1);
    float n2 = fmaxf(fminf(m1, o1), fmaxf(m2, o2));
    m1 = n1; m2 = n2;
}

// ---------------------------------------------------------------------------
// Kernel 1: one warp per (batch, point, bilinear row). 12288 warps.
// Each warp: 8 loads (2 x-corners x 4 channel chunks) -> top2 -> row partial.
// ---------------------------------------------------------------------------
__global__ void uncert_kernel(const float* __restrict__ outm,
                              const float* __restrict__ rand_over) {
    int gw = (blockIdx.x * blockDim.x + threadIdx.x) >> 5;
    int lane = threadIdx.x & 31;
    if (gw >= 2 * BB * KN) return;
    int r   = gw & 1;
    int idx = gw >> 1;          // b*KN + p
    int b = idx / KN;
    int p = idx - b * KN;

    float px = rand_over[idx * 2 + 0];
    float py = rand_over[idx * 2 + 1];
    float gx = px * (float)WO - 0.5f;
    float gy = py * (float)HO - 0.5f;
    float x0f = floorf(gx), y0f = floorf(gy);
    float wx = gx - x0f, wy = gy - y0f;
    int x0 = (int)x0f, y0 = (int)y0f;

    const float* base = outm + (long long)b * CO * HO * WO;
    bool xv0 = (x0 >= 0) && (x0 < WO);
    bool xv1 = (x0 + 1 >= 0) && (x0 + 1 < WO);
    int xc0 = min(max(x0, 0), WO - 1);
    int xc1 = min(max(x0 + 1, 0), WO - 1);

    int y = y0 + r;
    bool yv = (y >= 0) && (y < HO);
    int yc = min(max(y, 0), HO - 1);
    const float* rp = base + yc * WO;

    float v0[4], v1[4];
#pragma unroll
    for (int cc = 0; cc < 4; cc++) {
        long long co = (long long)(lane + cc * 32) * (HO * WO);
        v0[cc] = __ldg(rp + co + xc0);
        v1[cc] = __ldg(rp + co + xc1);
    }

    float a1 = -CUDART_INF_F, a2 = -CUDART_INF_F;   // corner x0
    float b1 = -CUDART_INF_F, b2 = -CUDART_INF_F;   // corner x0+1
#pragma unroll
    for (int cc = 0; cc < 4; cc++) {
        merge1(a1, a2, v0[cc]);
        merge1(b1, b2, v1[cc]);
    }
#pragma unroll
    for (int off = 16; off; off >>= 1) {
        merge2(a1, a2, __shfl_xor_sync(0xFFFFFFFFu, a1, off),
                       __shfl_xor_sync(0xFFFFFFFFu, a2, off));
        merge2(b1, b2, __shfl_xor_sync(0xFFFFFFFFu, b1, off),
                       __shfl_xor_sync(0xFFFFFFFFu, b2, off));
    }
    float e0 = (yv && xv0) ? (a2 - a1) : 0.f;   // -(top1 - top2), zero padded
    float e1 = (yv && xv1) ? (b2 - b1) : 0.f;
    float wyr = r ? wy : (1.f - wy);
    if (lane == 0)
        g_unc2[idx * 2 + r] = wyr * ((1.f - wx) * e0 + wx * e1);
}

// ---------------------------------------------------------------------------
// Kernel 2: exact top-192 per batch; register-resident bitonic, shfl stages
// ---------------------------------------------------------------------------
__global__ void topk_kernel(const float* __restrict__ rand_over,
                            const float* __restrict__ rand_cov,
                            float* __restrict__ points) {
    int b = blockIdx.x;
    int t = threadIdx.x;
    __shared__ unsigned long long sk[1024];

    unsigned long long key = 0ull;  // pad: sorts last (real keys have high word > 0)
    if (t < KN) {
        int idx = b * KN + t;
        float u = g_unc2[idx * 2 + 0] + g_unc2[idx * 2 + 1];
        unsigned ub = __float_as_uint(u);
        ub = (ub & 0x80000000u) ? ~ub : (ub | 0x80000000u);  // total order
        key = ((unsigned long long)ub << 32) | (unsigned long long)(0xFFFFFFFFu - (unsigned)t);
    }

    for (int k = 2; k <= 1024; k <<= 1) {
        for (int j = k >> 1; j; j >>= 1) {
            unsigned long long other;
            if (j >= 32) {
                __syncthreads();
                sk[t] = key;
                __syncthreads();
                other = sk[t ^ j];
            } else {
                other = __shfl_xor_sync(0xFFFFFFFFu, key, j);
            }
            bool iLower = ((t & j) == 0);
            bool desc   = ((t & k) == 0);
            unsigned long long mx = (key > other) ? key : other;
            unsigned long long mn = (key > other) ? other : key;
            key = (desc == iLower) ? mx : mn;   // overall descending
        }
    }

    if (t < BETA) {
        unsigned idx = 0xFFFFFFFFu - (unsigned)(key & 0xFFFFFFFFull);
        points[(b * NPTS + t) * 2 + 0] = rand_over[(b * KN + idx) * 2 + 0];
        points[(b * NPTS + t) * 2 + 1] = rand_over[(b * KN + idx) * 2 + 1];
    } else if (t < NPTS) {
        int i = t - BETA;
        points[(b * NPTS + t) * 2 + 0] = rand_cov[(b * (NPTS - BETA) + i) * 2 + 0];
        points[(b * NPTS + t) * 2 + 1] = rand_cov[(b * (NPTS - BETA) + i) * 2 + 1];
    }
}

// ---------------------------------------------------------------------------
// Kernel 3: gather coarse(128)+fine(64) at each point -> transposed g_featT
// block per (batch, point), 192 threads
// ---------------------------------------------------------------------------
__device__ __forceinline__ float bilerp_sample(const float* __restrict__ base,
                                               int H, int W, float px, float py) {
    float gx = px * (float)W - 0.5f;
    float gy = py * (float)H - 0.5f;
    float x0f = floorf(gx), y0f = floorf(gy);
    float wx = gx - x0f, wy = gy - y0f;
    int x0 = (int)x0f, y0 = (int)y0f;
    bool xv0 = (x0 >= 0) && (x0 < W);
    bool xv1 = (x0 + 1 >= 0) && (x0 + 1 < W);
    bool yv0 = (y0 >= 0) && (y0 < H);
    bool yv1 = (y0 + 1 >= 0) && (y0 + 1 < H);
    int xc0 = min(max(x0, 0), W - 1);
    int xc1 = min(max(x0 + 1, 0), W - 1);
    int yc0 = min(max(y0, 0), H - 1);
    int yc1 = min(max(y0 + 1, 0), H - 1);
    float v00 = (yv0 && xv0) ? __ldg(base + yc0 * W + xc0) : 0.f;
    float v01 = (yv0 && xv1) ? __ldg(base + yc0 * W + xc1) : 0.f;
    float v10 = (yv1 && xv0) ? __ldg(base + yc1 * W + xc0) : 0.f;
    float v11 = (yv1 && xv1) ? __ldg(base + yc1 * W + xc1) : 0.f;
    return v00 * (1.f - wx) * (1.f - wy) + v01 * wx * (1.f - wy)
         + v10 * (1.f - wx) * wy + v11 * wx * wy;
}

__global__ void gather_kernel(const float* __restrict__ outm,
                              const float* __restrict__ res2,
                              const float* __restrict__ points) {
    int bp = blockIdx.x;
    int b = bp / NPTS;
    int n = bp - b * NPTS;
    int t = threadIdx.x;

    float px = points[bp * 2 + 0];
    float py = points[bp * 2 + 1];

    float v;
    if (t < CO) {
        const float* base = outm + ((long long)(b * CO + t)) * (HO * WO);
        v = bilerp_sample(base, HO, WO, px, py);
    } else {
        const float* base = res2 + ((long long)(b * CF + (t - CO))) * (HF * WF);
        v = bilerp_sample(base, HF, WF, px, py);
    }
    g_featT[((long long)b * CFEAT + t) * NPTS + n] = v;
}

// ---------------------------------------------------------------------------
// Kernel 4: rend[b,o,n] = weight[o,:] . featT[b,:,n] + bias[o]
// block = 8 points x 128 out channels, 256 threads; featT rows are n-contiguous
// ---------------------------------------------------------------------------
__global__ __launch_bounds__(256) void gemm_kernel(
        const float* __restrict__ weight,
        const float* __restrict__ bias,
        float* __restrict__ rend) {
    __shared__ __align__(16) float fs[CFEAT * PTS];   // [k][p], 6 KB

    int blk = blockIdx.x;
    int b  = blk / (NPTS / PTS);
    int n0 = (blk % (NPTS / PTS)) * PTS;
    int tid = threadIdx.x;

    // load 192 x 8 tile: contiguous float4 rows from g_featT
    const float* src = g_featT + (long long)b * CFEAT * NPTS + n0;
#pragma unroll
    for (int j = tid; j < CFEAT * PTS / 4; j += 256) {
        int k = j >> 1;                 // PTS/4 = 2 float4 per row
        int part = j & 1;
        reinterpret_cast<float4*>(fs)[j] =
            *reinterpret_cast<const float4*>(src + (long long)k * NPTS + part * 4);
    }
    __syncthreads();

    int t  = tid & 127;   // out channel
    int ty = tid >> 7;    // 0..1 -> points ty*4 .. ty*4+3

    unsigned long long acc0 = 0ull, acc1 = 0ull;
    const float4* wr = reinterpret_cast<const float4*>(weight + t * CFEAT);
    const float* fbase = fs + ty * 4;

#pragma unroll
    for (int i = 0; i < CFEAT / 4; i++) {
        float4 w4 = __ldg(&wr[i]);
#pragma unroll
        for (int kk = 0; kk < 4; kk++) {
            float wv = (kk == 0) ? w4.x : (kk == 1) ? w4.y : (kk == 2) ? w4.z : w4.w;
            unsigned long long wp;
            PACK_F32X2(wp, wv, wv);
            const ulonglong2 ff = *reinterpret_cast<const ulonglong2*>(
                fbase + (i * 4 + kk) * PTS);
            FFMA2(acc0, wp, ff.x);
            FFMA2(acc1, wp, ff.y);
        }
    }

    float bv = bias[t];
    float4 outv;
    outv.x = __uint_as_float((unsigned)(acc0 & 0xFFFFFFFFull)) + bv;
    outv.y = __uint_as_float((unsigned)(acc0 >> 32)) + bv;
    outv.z = __uint_as_float((unsigned)(acc1 & 0xFFFFFFFFull)) + bv;
    outv.w = __uint_as_float((unsigned)(acc1 >> 32)) + bv;
    *reinterpret_cast<float4*>(rend + ((long long)b * CO + t) * NPTS + n0 + ty * 4) = outv;
}

// ---------------------------------------------------------------------------
// Launch
// ---------------------------------------------------------------------------
extern "C" void kernel_launch(void* const* d_in, const int* in_sizes, int n_in,
                              void* d_out, int out_size) {
    // metadata order: x, res2, out, rand_over, rand_cov, weight, bias
    const float* res2      = (const float*)d_in[1];
    const float* outm      = (const float*)d_in[2];
    const float* rand_over = (const float*)d_in[3];
    const float* rand_cov  = (const float*)d_in[4];
    const float* weight    = (const float*)d_in[5];
    const float* bias      = (const float*)d_in[6];

    float* rend   = (float*)d_out;                       // [B,128,256]
    float* points = (float*)d_out + BB * CO * NPTS;      // [B,256,2]

    // 2 warps (one per bilinear row) per oversampled point: 12288 warps
    uncert_kernel<<<(2 * BB * KN) / 8, 256>>>(outm, rand_over);
    topk_kernel<<<BB, 1024>>>(rand_over, rand_cov, points);
    gather_kernel<<<BB * NPTS, CFEAT>>>(outm, res2, points);
    gemm_kernel<<<BB * (NPTS / PTS), 256>>>(weight, bias, rend);
}

// round 7
// speedup vs baseline: 1.0699x; 1.0699x over previous
#include <cuda_runtime.h>
#include <math_constants.h>

// Problem constants (fixed shapes from setup_inputs)
#define BB   8      // batch
#define NPTS 256    // N = 4096/16
#define BETA 192    // 0.75*N
#define KN   768    // 3*N oversampled points
#define CO   128    // out channels
#define HO   256
#define WO   256
#define CF   64     // res2 channels
#define HF   512
#define WF   512
#define CFEAT (CO + CF)   // 192

__device__ float g_unc[BB * KN];
__device__ __align__(16) float g_featT[BB * CFEAT * NPTS];   // [B, 192, N]

#define PACK_F32X2(out, lo, hi) \
    asm("mov.b64 %0, {%1, %2};" : "=l"(out) : "f"(lo), "f"(hi))
#define FFMA2(acc, a, b) \
    asm("fma.rn.f32x2 %0, %1, %2, %0;" : "+l"(acc) : "l"(a), "l"(b))

// select element d (0..3) of a float4; d is warp-uniform small int
__device__ __forceinline__ float pick4(float4 q, int d) {
    float v = (d == 1) ? q.y : q.x;
    v = (d == 2) ? q.z : v;
    v = (d == 3) ? q.w : v;
    return v;
}

// merge running top2 (m1>=m2) with single value v
__device__ __forceinline__ void merge1(float &m1, float &m2, float v) {
    float n1 = fmaxf(m1, v);
    m2 = fmaxf(fminf(m1, v), m2);
    m1 = n1;
}
// merge running top2 with another pair (o1>=o2)
__device__ __forceinline__ void merge2(float &m1, float &m2, float o1, float o2) {
    float n1 = fmaxf(m1, o1);
    float n2 = fmaxf(fminf(m1, o1), fmaxf(m2, o2));
    m1 = n1; m2 = n2;
}

// ---------------------------------------------------------------------------
// Kernel 1: per-point uncertainty. One warp per point; x-corner pair fetched
// with one aligned float4 (plus warp-uniform extra load in the 12.5% case).
// ---------------------------------------------------------------------------
__global__ void uncert_kernel(const float* __restrict__ outm,
                              const float* __restrict__ rand_over) {
    int warp = (blockIdx.x * blockDim.x + threadIdx.x) >> 5;
    int lane = threadIdx.x & 31;
    if (warp >= BB * KN) return;
    int b = warp / KN;
    int p = warp - b * KN;

    float px = rand_over[(b * KN + p) * 2 + 0];
    float py = rand_over[(b * KN + p) * 2 + 1];
    float gx = px * (float)WO - 0.5f;
    float gy = py * (float)HO - 0.5f;
    float x0f = floorf(gx), y0f = floorf(gy);
    float wx = gx - x0f, wy = gy - y0f;
    int x0 = (int)x0f, y0 = (int)y0f;

    const float* base = outm + (long long)b * CO * HO * WO;
    bool xv0 = (x0 >= 0) && (x0 < WO);
    bool xv1 = (x0 + 1 >= 0) && (x0 + 1 < WO);
    bool yv0 = (y0 >= 0) && (y0 < HO);
    bool yv1 = (y0 + 1 >= 0) && (y0 + 1 < HO);
    int xc0 = min(max(x0, 0), WO - 1);
    int xc1 = min(max(x0 + 1, 0), WO - 1);
    int yc0 = min(max(y0, 0), HO - 1);
    int yc1 = min(max(y0 + 1, 0), HO - 1);

    int bx = xc0 & ~3;          // aligned float4 base
    int d0 = xc0 - bx;          // 0..3
    int d1 = xc1 - bx;          // 0..4 (4 => crosses into next float4)
    bool extra = (d1 == 4);     // warp-uniform

    const float* r0 = base + yc0 * WO;
    const float* r1 = base + yc1 * WO;

    // batched loads: 8 float4 (2 rows x 4 channel chunks), high MLP
    float4 q0[4], q1[4];
#pragma unroll
    for (int cc = 0; cc < 4; cc++) {
        long long co = (long long)(lane + cc * 32) * (HO * WO);
        q0[cc] = __ldg(reinterpret_cast<const float4*>(r0 + co + bx));
        q1[cc] = __ldg(reinterpret_cast<const float4*>(r1 + co + bx));
    }
    float vb0[4], vb1[4];
    if (extra) {
#pragma unroll
        for (int cc = 0; cc < 4; cc++) {
            long long co = (long long)(lane + cc * 32) * (HO * WO);
            vb0[cc] = __ldg(r0 + co + xc1);
            vb1[cc] = __ldg(r1 + co + xc1);
        }
    } else {
#pragma unroll
        for (int cc = 0; cc < 4; cc++) {
            vb0[cc] = pick4(q0[cc], d1);
            vb1[cc] = pick4(q1[cc], d1);
        }
    }

    float a1 = -CUDART_INF_F, a2 = -CUDART_INF_F;   // (y0,   x0)
    float b1 = -CUDART_INF_F, b2 = -CUDART_INF_F;   // (y0,   x0+1)
    float c1 = -CUDART_INF_F, c2 = -CUDART_INF_F;   // (y0+1, x0)
    float d1v = -CUDART_INF_F, d2v = -CUDART_INF_F; // (y0+1, x0+1)
#pragma unroll
    for (int cc = 0; cc < 4; cc++) {
        merge1(a1, a2, pick4(q0[cc], d0));
        merge1(b1, b2, vb0[cc]);
        merge1(c1, c2, pick4(q1[cc], d0));
        merge1(d1v, d2v, vb1[cc]);
    }
#pragma unroll
    for (int off = 16; off; off >>= 1) {
        merge2(a1, a2, __shfl_xor_sync(0xFFFFFFFFu, a1, off),
                       __shfl_xor_sync(0xFFFFFFFFu, a2, off));
        merge2(b1, b2, __shfl_xor_sync(0xFFFFFFFFu, b1, off),
                       __shfl_xor_sync(0xFFFFFFFFu, b2, off));
        merge2(c1, c2, __shfl_xor_sync(0xFFFFFFFFu, c1, off),
                       __shfl_xor_sync(0xFFFFFFFFu, c2, off));
        merge2(d1v, d2v, __shfl_xor_sync(0xFFFFFFFFu, d1v, off),
                         __shfl_xor_sync(0xFFFFFFFFu, d2v, off));
    }
    float e00 = (yv0 && xv0) ? (a2 - a1) : 0.f;   // -(top1 - top2), zero padded
    float e01 = (yv0 && xv1) ? (b2 - b1) : 0.f;
    float e10 = (yv1 && xv0) ? (c2 - c1) : 0.f;
    float e11 = (yv1 && xv1) ? (d2v - d1v) : 0.f;
    float unc = (1.f - wy) * ((1.f - wx) * e00 + wx * e01)
              +        wy  * ((1.f - wx) * e10 + wx * e11);
    if (lane == 0) g_unc[b * KN + p] = unc;
}

// ---------------------------------------------------------------------------
// Kernel 2: exact top-192 per batch; register-resident bitonic, shfl stages
// ---------------------------------------------------------------------------
__global__ void topk_kernel(const float* __restrict__ rand_over,
                            const float* __restrict__ rand_cov,
                            float* __restrict__ points) {
    int b = blockIdx.x;
    int t = threadIdx.x;
    __shared__ unsigned long long sk[1024];

    unsigned long long key = 0ull;  // pad: sorts last (real keys have high word > 0)
    if (t < KN) {
        float u = g_unc[b * KN + t];
        unsigned ub = __float_as_uint(u);
        ub = (ub & 0x80000000u) ? ~ub : (ub | 0x80000000u);  // total order
        key = ((unsigned long long)ub << 32) | (unsigned long long)(0xFFFFFFFFu - (unsigned)t);
    }

    for (int k = 2; k <= 1024; k <<= 1) {
        for (int j = k >> 1; j; j >>= 1) {
            unsigned long long other;
            if (j >= 32) {
                __syncthreads();
                sk[t] = key;
                __syncthreads();
                other = sk[t ^ j];
            } else {
                other = __shfl_xor_sync(0xFFFFFFFFu, key, j);
            }
            bool iLower = ((t & j) == 0);
            bool desc   = ((t & k) == 0);
            unsigned long long mx = (key > other) ? key : other;
            unsigned long long mn = (key > other) ? other : key;
            key = (desc == iLower) ? mx : mn;   // overall descending
        }
    }

    if (t < BETA) {
        unsigned idx = 0xFFFFFFFFu - (unsigned)(key & 0xFFFFFFFFull);
        points[(b * NPTS + t) * 2 + 0] = rand_over[(b * KN + idx) * 2 + 0];
        points[(b * NPTS + t) * 2 + 1] = rand_over[(b * KN + idx) * 2 + 1];
    } else if (t < NPTS) {
        int i = t - BETA;
        points[(b * NPTS + t) * 2 + 0] = rand_cov[(b * (NPTS - BETA) + i) * 2 + 0];
        points[(b * NPTS + t) * 2 + 1] = rand_cov[(b * (NPTS - BETA) + i) * 2 + 1];
    }
}

// ---------------------------------------------------------------------------
// Kernel 3: gather coarse(128)+fine(64) at each point -> transposed g_featT
// block per (batch, point), 192 threads; x-corner pair via aligned float4
// ---------------------------------------------------------------------------
__device__ __forceinline__ float bilerp_sample(const float* __restrict__ base,
                                               int H, int W, float px, float py) {
    float gx = px * (float)W - 0.5f;
    float gy = py * (float)H - 0.5f;
    float x0f = floorf(gx), y0f = floorf(gy);
    float wx = gx - x0f, wy = gy - y0f;
    int x0 = (int)x0f, y0 = (int)y0f;
    bool xv0 = (x0 >= 0) && (x0 < W);
    bool xv1 = (x0 + 1 >= 0) && (x0 + 1 < W);
    bool yv0 = (y0 >= 0) && (y0 < H);
    bool yv1 = (y0 + 1 >= 0) && (y0 + 1 < H);
    int xc0 = min(max(x0, 0), W - 1);
    int xc1 = min(max(x0 + 1, 0), W - 1);
    int yc0 = min(max(y0, 0), H - 1);
    int yc1 = min(max(y0 + 1, 0), H - 1);

    int bx = xc0 & ~3;
    int d0 = xc0 - bx;
    int d1 = xc1 - bx;
    const float* r0 = base + yc0 * W;
    const float* r1 = base + yc1 * W;
    float4 qa = __ldg(reinterpret_cast<const float4*>(r0 + bx));
    float4 qb = __ldg(reinterpret_cast<const float4*>(r1 + bx));
    float v00 = pick4(qa, d0);
    float v10 = pick4(qb, d0);
    float v01, v11;
    if (d1 == 4) {                       // warp-uniform (lanes share the point)
        v01 = __ldg(r0 + xc1);
        v11 = __ldg(r1 + xc1);
    } else {
        v01 = pick4(qa, d1);
        v11 = pick4(qb, d1);
    }
    v00 = (yv0 && xv0) ? v00 : 0.f;
    v01 = (yv0 && xv1) ? v01 : 0.f;
    v10 = (yv1 && xv0) ? v10 : 0.f;
    v11 = (yv1 && xv1) ? v11 : 0.f;
    return v00 * (1.f - wx) * (1.f - wy) + v01 * wx * (1.f - wy)
         + v10 * (1.f - wx) * wy + v11 * wx * wy;
}

__global__ void gather_kernel(const float* __restrict__ outm,
                              const float* __restrict__ res2,
                              const float* __restrict__ points) {
    int bp = blockIdx.x;
    int b = bp / NPTS;
    int n = bp - b * NPTS;
    int t = threadIdx.x;

    float px = points[bp * 2 + 0];
    float py = points[bp * 2 + 1];

    float v;
    if (t < CO) {
        const float* base = outm + ((long long)(b * CO + t)) * (HO * WO);
        v = bilerp_sample(base, HO, WO, px, py);
    } else {
        const float* base = res2 + ((long long)(b * CF + (t - CO))) * (HF * WF);
        v = bilerp_sample(base, HF, WF, px, py);
    }
    g_featT[((long long)b * CFEAT + t) * NPTS + n] = v;
}

// ---------------------------------------------------------------------------
// Kernel 4: rend = weight . featT + bias.
// Block: 64 o x 32 n, 128 threads, thread = 2 o x 8 n. Weight staged in smem
// (64x96 per k-half, pad to 97 -> conflict-free), f tile broadcast LDS.128.
// grid = BB * (NPTS/32) * 2 = 128 blocks (single wave).
// ---------------------------------------------------------------------------
__global__ __launch_bounds__(128) void gemm_kernel(
        const float* __restrict__ weight,
        const float* __restrict__ bias,
        float* __restrict__ rend) {
    __shared__ float ws[64][97];                     // 24.8 KB
    __shared__ __align__(16) float fs[96][32];       // 12 KB

    int blk = blockIdx.x;
    int oh =  blk & 1;            // o half
    int nt = (blk >> 1) & 7;      // n tile
    int b  =  blk >> 4;
    int obase = oh * 64;
    int n0 = nt * 32;
    int tid = threadIdx.x;
    int og = tid & 31;            // o's: obase+og, obase+og+32
    int ng = tid >> 5;            // n group: n0 + ng*8 .. +7

    unsigned long long acc[8];
#pragma unroll
    for (int i = 0; i < 8; i++) acc[i] = 0ull;

#pragma unroll
    for (int h = 0; h < 2; h++) {
        __syncthreads();
        // stage weight half: rows obase..obase+63, k in [h*96, h*96+96)
        for (int j = tid; j < 64 * 24; j += 128) {
            int row = j / 24, part = j % 24;
            float4 w4 = *reinterpret_cast<const float4*>(
                weight + (obase + row) * CFEAT + h * 96 + part * 4);
            ws[row][part * 4 + 0] = w4.x;
            ws[row][part * 4 + 1] = w4.y;
            ws[row][part * 4 + 2] = w4.z;
            ws[row][part * 4 + 3] = w4.w;
        }
        // stage f half: k rows h*96..+95, n0..n0+31
        for (int j = tid; j < 96 * 8; j += 128) {
            int row = j / 8, part = j % 8;
            *reinterpret_cast<float4*>(&fs[row][part * 4]) =
                *reinterpret_cast<const float4*>(
                    g_featT + ((long long)b * CFEAT + h * 96 + row) * NPTS + n0 + part * 4);
        }
        __syncthreads();

#pragma unroll 4
        for (int k = 0; k < 96; k++) {
            float w0 = ws[og][k];
            float w1 = ws[og + 32][k];
            unsigned long long wp0, wp1;
            PACK_F32X2(wp0, w0, w0);
            PACK_F32X2(wp1, w1, w1);
            ulonglong2 fA = *reinterpret_cast<const ulonglong2*>(&fs[k][ng * 8]);
            ulonglong2 fB = *reinterpret_cast<const ulonglong2*>(&fs[k][ng * 8 + 4]);
            FFMA2(acc[0], wp0, fA.x);
            FFMA2(acc[1], wp0, fA.y);
            FFMA2(acc[2], wp0, fB.x);
            FFMA2(acc[3], wp0, fB.y);
            FFMA2(acc[4], wp1, fA.x);
            FFMA2(acc[5], wp1, fA.y);
            FFMA2(acc[6], wp1, fB.x);
            FFMA2(acc[7], wp1, fB.y);
        }
    }

    float bv0 = bias[obase + og];
    float bv1 = bias[obase + og + 32];
    float4 o0a, o0b, o1a, o1b;
    o0a.x = __uint_as_float((unsigned)(acc[0] & 0xFFFFFFFFull)) + bv0;
    o0a.y = __uint_as_float((unsigned)(acc[0] >> 32)) + bv0;
    o0a.z = __uint_as_float((unsigned)(acc[1] & 0xFFFFFFFFull)) + bv0;
    o0a.w = __uint_as_float((unsigned)(acc[1] >> 32)) + bv0;
    o0b.x = __uint_as_float((unsigned)(acc[2] & 0xFFFFFFFFull)) + bv0;
    o0b.y = __uint_as_float((unsigned)(acc[2] >> 32)) + bv0;
    o0b.z = __uint_as_float((unsigned)(acc[3] & 0xFFFFFFFFull)) + bv0;
    o0b.w = __uint_as_float((unsigned)(acc[3] >> 32)) + bv0;
    o1a.x = __uint_as_float((unsigned)(acc[4] & 0xFFFFFFFFull)) + bv1;
    o1a.y = __uint_as_float((unsigned)(acc[4] >> 32)) + bv1;
    o1a.z = __uint_as_float((unsigned)(acc[5] & 0xFFFFFFFFull)) + bv1;
    o1a.w = __uint_as_float((unsigned)(acc[5] >> 32)) + bv1;
    o1b.x = __uint_as_float((unsigned)(acc[6] & 0xFFFFFFFFull)) + bv1;
    o1b.y = __uint_as_float((unsigned)(acc[6] >> 32)) + bv1;
    o1b.z = __uint_as_float((unsigned)(acc[7] & 0xFFFFFFFFull)) + bv1;
    o1b.w = __uint_as_float((unsigned)(acc[7] >> 32)) + bv1;

    long long r0 = ((long long)b * CO + obase + og) * NPTS + n0 + ng * 8;
    long long r1 = ((long long)b * CO + obase + og + 32) * NPTS + n0 + ng * 8;
    *reinterpret_cast<float4*>(rend + r0)     = o0a;
    *reinterpret_cast<float4*>(rend + r0 + 4) = o0b;
    *reinterpret_cast<float4*>(rend + r1)     = o1a;
    *reinterpret_cast<float4*>(rend + r1 + 4) = o1b;
}

// ---------------------------------------------------------------------------
// Launch
// ---------------------------------------------------------------------------
extern "C" void kernel_launch(void* const* d_in, const int* in_sizes, int n_in,
                              void* d_out, int out_size) {
    // metadata order: x, res2, out, rand_over, rand_cov, weight, bias
    const float* res2      = (const float*)d_in[1];
    const float* outm      = (const float*)d_in[2];
    const float* rand_over = (const float*)d_in[3];
    const float* rand_cov  = (const float*)d_in[4];
    const float* weight    = (const float*)d_in[5];
    const float* bias      = (const float*)d_in[6];

    float* rend   = (float*)d_out;                       // [B,128,256]
    float* points = (float*)d_out + BB * CO * NPTS;      // [B,256,2]

    uncert_kernel<<<(BB * KN) / 8, 256>>>(outm, rand_over);
    topk_kernel<<<BB, 1024>>>(rand_over, rand_cov, points);
    gather_kernel<<<BB * NPTS, CFEAT>>>(outm, res2, points);
    gemm_kernel<<<BB * (NPTS / 32) * 2, 128>>>(weight, bias, rend);
}